// round 15
// baseline (speedup 1.0000x reference)
#include <cuda_runtime.h>

#define NB 8
#define NS 2048
#define ND 768
#define NH 64
#define NQT 32            // q-tiles of 64
#define NSPL 4            // split-K factor
#define SKA 68            // attn smem stride (floats), 68 % 32 == 4 -> conflict-free LDSM
#define STG (64 * SKA)    // floats per attn K/V buffer

// g_Q (pre-scaled by 1/8), g_K: [b][n][h] tf32 bits.  g_V: [b][h][n] tf32 bits.
__device__ float g_Q[NB * NS * NH];
__device__ float g_K[NB * NS * NH];
__device__ float g_V[NB * NH * NS];

// split-K partials: [split][b][qt] -> 64x64 unnormalized O, plus per-row m,l
__device__ float g_Op[NSPL * NB * NQT * 64 * 64];
__device__ float g_M[NSPL * NB * NQT * 64];
__device__ float g_L[NSPL * NB * NQT * 64];

// ---------------------------------------------------------------------------
// helpers
// ---------------------------------------------------------------------------
__device__ __forceinline__ unsigned f2tf(float f) {
    unsigned u;
    asm("cvt.rna.tf32.f32 %0, %1;" : "=r"(u) : "f"(f));
    return u;
}
__device__ __forceinline__ uint4 f4tf(float4 v) {
    uint4 r;
    r.x = f2tf(v.x); r.y = f2tf(v.y); r.z = f2tf(v.z); r.w = f2tf(v.w);
    return r;
}
__device__ __forceinline__ void mma8(float c[4],
                                     unsigned a0, unsigned a1, unsigned a2, unsigned a3,
                                     unsigned b0, unsigned b1) {
    asm("mma.sync.aligned.m16n8k8.row.col.f32.tf32.tf32.f32 "
        "{%0,%1,%2,%3}, {%4,%5,%6,%7}, {%8,%9}, {%0,%1,%2,%3};"
        : "+f"(c[0]), "+f"(c[1]), "+f"(c[2]), "+f"(c[3])
        : "r"(a0), "r"(a1), "r"(a2), "r"(a3), "r"(b0), "r"(b1));
}
__device__ __forceinline__ void ldsm4(unsigned &r0, unsigned &r1,
                                      unsigned &r2, unsigned &r3, unsigned addr) {
    asm volatile("ldmatrix.sync.aligned.m8n8.x4.shared.b16 {%0,%1,%2,%3}, [%4];"
                 : "=r"(r0), "=r"(r1), "=r"(r2), "=r"(r3) : "r"(addr));
}
__device__ __forceinline__ void cpa16(unsigned dst, const void* src) {
    asm volatile("cp.async.cg.shared.global [%0], [%1], 16;"
                 :: "r"(dst), "l"(src));
}
#define CP_COMMIT() asm volatile("cp.async.commit_group;" ::: "memory")
#define CP_WAIT0()  asm volatile("cp.async.wait_group 0;" ::: "memory")

// ---------------------------------------------------------------------------
// Kernel 1: QKV projection via tf32 mma. Same tiling/loop as R13; ONLY change:
// Ws stored [n][k] (stride 36) and all fragments fetched via ldmatrix.x4
// (A pattern == attn aQ, B pattern == attn bK; both conflict-free).
// Epilogue: tf32 bits; Q pre-scaled by 0.125 (exact); V stored transposed.
// ---------------------------------------------------------------------------
#define XS_S 36
#define WS_S 36

__global__ __launch_bounds__(128, 3) void proj_kernel(
    const float* __restrict__ X,
    const float* __restrict__ Wq,
    const float* __restrict__ Wk,
    const float* __restrict__ Wv)
{
    const int z = blockIdx.z;
    const float* __restrict__ W = (z == 0) ? Wq : (z == 1) ? Wk : Wv;

    __shared__ float Xs[128 * XS_S];   // [m][k]  18.4 KB
    __shared__ float Ws[64 * WS_S];    // [n][k]   9.2 KB

    const int row0 = blockIdx.x * 128;
    const int tid  = threadIdx.x;
    const int lane = tid & 31;
    const int g    = lane >> 2;
    const int t    = lane & 3;
    const int mrow = (tid >> 5) * 32;

    float acc[2][8][4];
#pragma unroll
    for (int mt = 0; mt < 2; ++mt)
#pragma unroll
        for (int nt = 0; nt < 8; ++nt)
#pragma unroll
            for (int r = 0; r < 4; ++r) acc[mt][nt][r] = 0.0f;

    // loader mappings
    const int xr  = tid >> 3;           // 0..15
    const int xc  = (tid & 7) * 4;      // 0..28
    const int wk  = tid & 7;            // k within 8-block
    const int wn4 = (tid >> 3) * 4;     // 0..60

    // ldmatrix lane addresses
    const unsigned smbX = (unsigned)__cvta_generic_to_shared(Xs);
    const unsigned smbW = (unsigned)__cvta_generic_to_shared(Ws);
    const unsigned aX0 = smbX +
        (unsigned)(((mrow + (lane & 15)) * XS_S + (lane >> 4) * 4) * 4);
    const unsigned aX1 = aX0 + 16u * XS_S * 4;
    const int rowB = (lane & 7) | ((lane >> 1) & 8);
    const int colB = ((lane >> 3) & 1) * 4;
    const unsigned bW = smbW + (unsigned)((rowB * WS_S + colB) * 4);

    for (int kk = 0; kk < ND; kk += 32) {
        // X tile 128x32, tf32-rounded, [m][k]
#pragma unroll
        for (int it = 0; it < 8; ++it) {
            const int r = xr + it * 16;
            float4 v = *reinterpret_cast<const float4*>(
                X + (size_t)(row0 + r) * ND + kk + xc);
            *reinterpret_cast<uint4*>(&Xs[r * XS_S + xc]) = f4tf(v);
        }
        // W tile 32x64 -> Ws[n][k], tf32-rounded, scalar transpose stores
#pragma unroll
        for (int it = 0; it < 4; ++it) {
            const int k = wk + it * 8;
            uint4 v = f4tf(*reinterpret_cast<const float4*>(
                W + (size_t)(kk + k) * NH + wn4));
            Ws[(wn4 + 0) * WS_S + k] = __uint_as_float(v.x);
            Ws[(wn4 + 1) * WS_S + k] = __uint_as_float(v.y);
            Ws[(wn4 + 2) * WS_S + k] = __uint_as_float(v.z);
            Ws[(wn4 + 3) * WS_S + k] = __uint_as_float(v.w);
        }
        __syncthreads();

#pragma unroll
        for (int dc = 0; dc < 4; ++dc) {
            unsigned a[2][4];
            ldsm4(a[0][0], a[0][1], a[0][2], a[0][3], aX0 + dc * 32);
            ldsm4(a[1][0], a[1][1], a[1][2], a[1][3], aX1 + dc * 32);
#pragma unroll
            for (int p = 0; p < 4; ++p) {
                unsigned b0, b1, b2, b3;
                ldsm4(b0, b1, b2, b3, bW + p * (16 * WS_S * 4) + dc * 32);
                mma8(acc[0][2 * p],     a[0][0], a[0][1], a[0][2], a[0][3], b0, b1);
                mma8(acc[0][2 * p + 1], a[0][0], a[0][1], a[0][2], a[0][3], b2, b3);
                mma8(acc[1][2 * p],     a[1][0], a[1][1], a[1][2], a[1][3], b0, b1);
                mma8(acc[1][2 * p + 1], a[1][0], a[1][1], a[1][2], a[1][3], b2, b3);
            }
        }
        __syncthreads();
    }

    // epilogue: tf32-round; Q pre-scaled by 1/8 (exact); V transposed
    const float sc = (z == 0) ? 0.125f : 1.0f;
#pragma unroll
    for (int mt = 0; mt < 2; ++mt) {
        const int rb = row0 + mrow + mt * 16;
#pragma unroll
        for (int nt = 0; nt < 8; ++nt) {
            const int col = nt * 8 + 2 * t;
            const int rA = rb + g, rB2 = rb + g + 8;
            const unsigned v0 = f2tf(acc[mt][nt][0] * sc);
            const unsigned v1 = f2tf(acc[mt][nt][1] * sc);
            const unsigned v2 = f2tf(acc[mt][nt][2] * sc);
            const unsigned v3 = f2tf(acc[mt][nt][3] * sc);
            if (z == 2) {
                const int bA = rA >> 11, nA = rA & 2047;
                const int bB = rB2 >> 11, nB = rB2 & 2047;
                g_V[((size_t)bA * NH + col)     * NS + nA] = __uint_as_float(v0);
                g_V[((size_t)bA * NH + col + 1) * NS + nA] = __uint_as_float(v1);
                g_V[((size_t)bB * NH + col)     * NS + nB] = __uint_as_float(v2);
                g_V[((size_t)bB * NH + col + 1) * NS + nB] = __uint_as_float(v3);
            } else {
                float* __restrict__ Out = (z == 0) ? g_Q : g_K;
                *reinterpret_cast<uint2*>(Out + (size_t)rA * NH + col) =
                    make_uint2(v0, v1);
                *reinterpret_cast<uint2*>(Out + (size_t)rB2 * NH + col) =
                    make_uint2(v2, v3);
            }
        }
    }
}

// ---------------------------------------------------------------------------
// Kernel 2: causal flash attention, tf32 mma + ldmatrix + split-K x4 +
// cp.async double-buffered K/V pipeline. (R13, minus the 0.125 scaling,
// which is now folded into Q — bit-identical.)
// ---------------------------------------------------------------------------
__global__ __launch_bounds__(128, 3) void attn_kernel()
{
    extern __shared__ float sm[];

    const int b    = blockIdx.y;
    const int qt   = (NQT - 1) - blockIdx.x;
    const int spl  = blockIdx.z;
    const int q0   = qt * 64;
    const int tid  = threadIdx.x;
    const int wrp  = tid >> 5;
    const int lane = tid & 31;
    const int g    = lane >> 2;
    const int t    = lane & 3;
    const int w16  = wrp * 16;

    const int T  = qt + 1;
    const int tb = (T * spl) >> 2;
    const int te = (T * (spl + 1)) >> 2;

    const float* __restrict__ Qb = g_Q + (size_t)b * NS * NH;
    const float* __restrict__ Kb = g_K + (size_t)b * NS * NH;
    const float* __restrict__ Vb = g_V + (size_t)b * NH * NS;

    const unsigned smb = (unsigned)__cvta_generic_to_shared(sm);
    const int rowA = w16 + (lane & 15);
    const int colA = (lane >> 4) * 4;
    const unsigned fragA = (unsigned)((rowA * SKA + colA) * 4);
    const int rowB = (lane & 7) | ((lane >> 1) & 8);
    const int colB = ((lane >> 3) & 1) * 4;
    const unsigned fragB = (unsigned)((rowB * SKA + colB) * 4);
    const unsigned bufK[2] = { 0u, 2u * STG * 4 };
    const unsigned bufV[2] = { 1u * STG * 4, 3u * STG * 4 };

    const int lr  = tid >> 1;
    const int lc  = (tid & 1) * 32;
    const unsigned kdst0 = (unsigned)((lr * SKA + lc) * 4);
    const float* ksrc_base = Kb + (size_t)lr * NH + lc;
    const float* vsrc_base = Vb + (size_t)lr * NS + lc;

    unsigned qf[8][4];
    if (tb < te) {
        const float4* qp = reinterpret_cast<const float4*>(
            Qb + (size_t)(q0 + lr) * NH + lc);
#pragma unroll
        for (int u = 0; u < 8; ++u)
            *reinterpret_cast<float4*>(&sm[lr * SKA + lc + u * 4]) = qp[u];
        __syncthreads();
#pragma unroll
        for (int dc = 0; dc < 8; ++dc)
            ldsm4(qf[dc][0], qf[dc][1], qf[dc][2], qf[dc][3],
                  smb + fragA + dc * 32);
        __syncthreads();

        {
            const int k0 = tb * 64;
            const float* ks = ksrc_base + (size_t)k0 * NH;
            const float* vs = vsrc_base + k0;
#pragma unroll
            for (int u = 0; u < 8; ++u) {
                cpa16(smb + bufK[0] + kdst0 + u * 16, ks + u * 4);
                cpa16(smb + bufV[0] + kdst0 + u * 16, vs + u * 4);
            }
            CP_COMMIT();
        }
    }

    float o[8][4];
#pragma unroll
    for (int nt = 0; nt < 8; ++nt)
#pragma unroll
        for (int r = 0; r < 4; ++r) o[nt][r] = 0.0f;
    float mA = -1e30f, mB = -1e30f;
    float lA = 0.0f,   lB = 0.0f;

    int cur = 0;
    for (int kt = tb; kt < te; ++kt) {
        CP_WAIT0();
        __syncthreads();

        if (kt + 1 < te) {
            const int k0n = (kt + 1) * 64;
            const float* ks = ksrc_base + (size_t)k0n * NH;
            const float* vs = vsrc_base + k0n;
#pragma unroll
            for (int u = 0; u < 8; ++u) {
                cpa16(smb + bufK[cur ^ 1] + kdst0 + u * 16, ks + u * 4);
                cpa16(smb + bufV[cur ^ 1] + kdst0 + u * 16, vs + u * 4);
            }
            CP_COMMIT();
        }

        float s[8][4];
#pragma unroll
        for (int nt = 0; nt < 8; ++nt)
#pragma unroll
            for (int r = 0; r < 4; ++r) s[nt][r] = 0.0f;

        const unsigned bKc = smb + bufK[cur] + fragB;
#pragma unroll
        for (int dc = 0; dc < 8; ++dc) {
#pragma unroll
            for (int p = 0; p < 4; ++p) {
                unsigned b0, b1, b2, b3;
                ldsm4(b0, b1, b2, b3, bKc + p * (16 * SKA * 4) + dc * 32);
                mma8(s[2 * p],     qf[dc][0], qf[dc][1], qf[dc][2], qf[dc][3], b0, b1);
                mma8(s[2 * p + 1], qf[dc][0], qf[dc][1], qf[dc][2], qf[dc][3], b2, b3);
            }
        }

        if (kt == qt) {   // causal mask on the diagonal tile (S already scaled)
            const int rA = w16 + g, rB2 = w16 + g + 8;
#pragma unroll
            for (int nt = 0; nt < 8; ++nt) {
                const int c0 = nt * 8 + 2 * t, c1 = c0 + 1;
                if (c0 > rA)  s[nt][0] = -1e30f;
                if (c1 > rA)  s[nt][1] = -1e30f;
                if (c0 > rB2) s[nt][2] = -1e30f;
                if (c1 > rB2) s[nt][3] = -1e30f;
            }
        }

        float cmA = -1e30f, cmB = -1e30f;
#pragma unroll
        for (int nt = 0; nt < 8; ++nt) {
            cmA = fmaxf(cmA, fmaxf(s[nt][0], s[nt][1]));
            cmB = fmaxf(cmB, fmaxf(s[nt][2], s[nt][3]));
        }
        cmA = fmaxf(cmA, __shfl_xor_sync(0xffffffffu, cmA, 1));
        cmA = fmaxf(cmA, __shfl_xor_sync(0xffffffffu, cmA, 2));
        cmB = fmaxf(cmB, __shfl_xor_sync(0xffffffffu, cmB, 1));
        cmB = fmaxf(cmB, __shfl_xor_sync(0xffffffffu, cmB, 2));

        const float mnA = fmaxf(mA, cmA);
        const float mnB = fmaxf(mB, cmB);
        const float cA  = __expf(mA - mnA);
        const float cB  = __expf(mB - mnB);
        mA = mnA; mB = mnB;
        lA *= cA; lB *= cB;
#pragma unroll
        for (int nt = 0; nt < 8; ++nt) {
            o[nt][0] *= cA; o[nt][1] *= cA;
            o[nt][2] *= cB; o[nt][3] *= cB;
        }
#pragma unroll
        for (int nt = 0; nt < 8; ++nt) {
            s[nt][0] = __expf(s[nt][0] - mnA);
            s[nt][1] = __expf(s[nt][1] - mnA);
            s[nt][2] = __expf(s[nt][2] - mnB);
            s[nt][3] = __expf(s[nt][3] - mnB);
            lA += s[nt][0] + s[nt][1];
            lB += s[nt][2] + s[nt][3];
        }

        __syncthreads();

        float* Kcur = sm + (cur ? 2 * STG : 0);
#pragma unroll
        for (int nt = 0; nt < 8; ++nt) {
            *reinterpret_cast<uint2*>(&Kcur[(w16 + g) * SKA + nt * 8 + 2 * t]) =
                make_uint2(f2tf(s[nt][0]), f2tf(s[nt][1]));
            *reinterpret_cast<uint2*>(&Kcur[(w16 + g + 8) * SKA + nt * 8 + 2 * t]) =
                make_uint2(f2tf(s[nt][2]), f2tf(s[nt][3]));
        }
        __syncwarp();

        const unsigned aPc = smb + bufK[cur] + fragA;
        const unsigned bVc = smb + bufV[cur] + fragB;
#pragma unroll
        for (int kc = 0; kc < 8; ++kc) {
            unsigned a0, a1, a2, a3;
            ldsm4(a0, a1, a2, a3, aPc + kc * 32);
#pragma unroll
            for (int p = 0; p < 4; ++p) {
                unsigned b0, b1, b2, b3;
                ldsm4(b0, b1, b2, b3, bVc + p * (16 * SKA * 4) + kc * 32);
                mma8(o[2 * p],     a0, a1, a2, a3, b0, b1);
                mma8(o[2 * p + 1], a0, a1, a2, a3, b2, b3);
            }
        }

        cur ^= 1;
    }

    lA += __shfl_xor_sync(0xffffffffu, lA, 1);
    lA += __shfl_xor_sync(0xffffffffu, lA, 2);
    lB += __shfl_xor_sync(0xffffffffu, lB, 1);
    lB += __shfl_xor_sync(0xffffffffu, lB, 2);

    const size_t slot = ((size_t)spl * NB + b) * NQT + qt;
    float* op = g_Op + slot * 64 * 64;
#pragma unroll
    for (int nt = 0; nt < 8; ++nt) {
        *reinterpret_cast<float2*>(op + (w16 + g) * 64 + nt * 8 + 2 * t) =
            make_float2(o[nt][0], o[nt][1]);
        *reinterpret_cast<float2*>(op + (w16 + g + 8) * 64 + nt * 8 + 2 * t) =
            make_float2(o[nt][2], o[nt][3]);
    }
    if (t == 0) {
        g_M[slot * 64 + w16 + g]     = mA;
        g_M[slot * 64 + w16 + g + 8] = mB;
        g_L[slot * 64 + w16 + g]     = lA;
        g_L[slot * 64 + w16 + g + 8] = lB;
    }
}

// ---------------------------------------------------------------------------
// Kernel 3: merge NSPL split-K partials. grid (32, NB, 2), 128 threads:
// z-half handles 32 q-rows (2x block parallelism for latency hiding).
// ---------------------------------------------------------------------------
__global__ __launch_bounds__(128) void merge_kernel(float* __restrict__ out)
{
    const int qt  = blockIdx.x;
    const int b   = blockIdx.y;
    const int tid = threadIdx.x;
    const int r   = blockIdx.z * 32 + (tid >> 2);
    const int cs  = (tid & 3) * 16;

    size_t slot[NSPL];
    float  m[NSPL], l[NSPL];
    float  M = -1e30f;
#pragma unroll
    for (int s = 0; s < NSPL; ++s) {
        slot[s] = ((size_t)s * NB + b) * NQT + qt;
        m[s] = g_M[slot[s] * 64 + r];
        l[s] = g_L[slot[s] * 64 + r];
        M = fmaxf(M, m[s]);
    }
    float f[NSPL], den = 0.0f;
#pragma unroll
    for (int s = 0; s < NSPL; ++s) {
        f[s] = __expf(m[s] - M);     // empty split: exp(-1e30 - M) = 0
        den += l[s] * f[s];
    }
    const float inv = 1.0f / den;
#pragma unroll
    for (int s = 0; s < NSPL; ++s) f[s] *= inv;

    float4* po = reinterpret_cast<float4*>(
        out + ((size_t)b * NS + qt * 64 + r) * NH + cs);

#pragma unroll
    for (int u = 0; u < 4; ++u) {
        float4 acc = make_float4(0.f, 0.f, 0.f, 0.f);
#pragma unroll
        for (int s = 0; s < NSPL; ++s) {
            float4 v = *reinterpret_cast<const float4*>(
                g_Op + slot[s] * 4096 + r * 64 + cs + u * 4);
            acc.x += v.x * f[s]; acc.y += v.y * f[s];
            acc.z += v.z * f[s]; acc.w += v.w * f[s];
        }
        po[u] = acc;
    }
}

// ---------------------------------------------------------------------------
extern "C" void kernel_launch(void* const* d_in, const int* in_sizes, int n_in,
                              void* d_out, int out_size)
{
    const float* X  = (const float*)d_in[0];
    const float* Wq = (const float*)d_in[1];
    const float* Wk = (const float*)d_in[2];
    const float* Wv = (const float*)d_in[3];
    float* out = (float*)d_out;

    const int attn_smem = 4 * STG * (int)sizeof(float);   // 69632 B
    cudaFuncSetAttribute(attn_kernel,
                         cudaFuncAttributeMaxDynamicSharedMemorySize, attn_smem);

    proj_kernel<<<dim3((NB * NS) / 128, 1, 3), 128>>>(X, Wq, Wk, Wv);
    attn_kernel<<<dim3(NQT, NB, NSPL), 128, attn_smem>>>();
    merge_kernel<<<dim3(NQT, NB, 2), 128>>>(out);
}

// round 16
// speedup vs baseline: 1.0983x; 1.0983x over previous
#include <cuda_runtime.h>

#define NB 8
#define NS 2048
#define ND 768
#define NH 64
#define NQT 32            // q-tiles of 64
#define NSPL 4            // split-K factor
#define SKA 68            // attn smem stride (floats), 68 % 32 == 4 -> conflict-free LDSM
#define STG (64 * SKA)    // floats per attn K/V buffer

// g_Q (pre-scaled by 1/8), g_K: [b][n][h] tf32 bits.  g_V: [b][h][n] tf32 bits.
__device__ float g_Q[NB * NS * NH];
__device__ float g_K[NB * NS * NH];
__device__ float g_V[NB * NH * NS];

// split-K partials: [split][b][qt] -> 64x64 unnormalized O, plus per-row m,l
__device__ float g_Op[NSPL * NB * NQT * 64 * 64];
__device__ float g_M[NSPL * NB * NQT * 64];
__device__ float g_L[NSPL * NB * NQT * 64];

// ---------------------------------------------------------------------------
// helpers
// ---------------------------------------------------------------------------
__device__ __forceinline__ unsigned f2tf(float f) {
    unsigned u;
    asm("cvt.rna.tf32.f32 %0, %1;" : "=r"(u) : "f"(f));
    return u;
}
__device__ __forceinline__ uint4 f4tf(float4 v) {
    uint4 r;
    r.x = f2tf(v.x); r.y = f2tf(v.y); r.z = f2tf(v.z); r.w = f2tf(v.w);
    return r;
}
__device__ __forceinline__ void mma8(float c[4],
                                     unsigned a0, unsigned a1, unsigned a2, unsigned a3,
                                     unsigned b0, unsigned b1) {
    asm("mma.sync.aligned.m16n8k8.row.col.f32.tf32.tf32.f32 "
        "{%0,%1,%2,%3}, {%4,%5,%6,%7}, {%8,%9}, {%0,%1,%2,%3};"
        : "+f"(c[0]), "+f"(c[1]), "+f"(c[2]), "+f"(c[3])
        : "r"(a0), "r"(a1), "r"(a2), "r"(a3), "r"(b0), "r"(b1));
}
__device__ __forceinline__ void ldsm4(unsigned &r0, unsigned &r1,
                                      unsigned &r2, unsigned &r3, unsigned addr) {
    asm volatile("ldmatrix.sync.aligned.m8n8.x4.shared.b16 {%0,%1,%2,%3}, [%4];"
                 : "=r"(r0), "=r"(r1), "=r"(r2), "=r"(r3) : "r"(addr));
}
__device__ __forceinline__ void cpa16(unsigned dst, const void* src) {
    asm volatile("cp.async.cg.shared.global [%0], [%1], 16;"
                 :: "r"(dst), "l"(src));
}
#define CP_COMMIT() asm volatile("cp.async.commit_group;" ::: "memory")
#define CP_WAIT0()  asm volatile("cp.async.wait_group 0;" ::: "memory")

// ---------------------------------------------------------------------------
// Kernel 1: QKV projection via tf32 mma — EXACT R13/R8 structure (proven).
// Only epilogue change: Q pre-scaled by 0.125 before tf32 rounding (exact),
// V stored transposed g_V[b][h][n]; all outputs tf32 bits.
// ---------------------------------------------------------------------------
#define XS_S 36
#define WS_S 72

__global__ __launch_bounds__(128, 3) void proj_kernel(
    const float* __restrict__ X,
    const float* __restrict__ Wq,
    const float* __restrict__ Wk,
    const float* __restrict__ Wv)
{
    const int z = blockIdx.z;
    const float* __restrict__ W = (z == 0) ? Wq : (z == 1) ? Wk : Wv;

    __shared__ float Xs[128 * XS_S];
    __shared__ float Ws[32 * WS_S];

    const int row0 = blockIdx.x * 128;
    const int tid  = threadIdx.x;
    const int wrp  = tid >> 5;
    const int lane = tid & 31;
    const int g    = lane >> 2;
    const int t    = lane & 3;
    const int mrow = wrp * 32;

    float acc[2][8][4];
#pragma unroll
    for (int mt = 0; mt < 2; ++mt)
#pragma unroll
        for (int nt = 0; nt < 8; ++nt)
#pragma unroll
            for (int r = 0; r < 4; ++r) acc[mt][nt][r] = 0.0f;

    const int xr = tid >> 3;
    const int xc = (tid & 7) * 4;
    const int wr = tid >> 4;
    const int wc = (tid & 15) * 4;

    for (int kk = 0; kk < ND; kk += 32) {
#pragma unroll
        for (int it = 0; it < 8; ++it) {
            const int r = xr + it * 16;
            float4 v = *reinterpret_cast<const float4*>(
                X + (size_t)(row0 + r) * ND + kk + xc);
            *reinterpret_cast<uint4*>(&Xs[r * XS_S + xc]) = f4tf(v);
        }
#pragma unroll
        for (int it = 0; it < 4; ++it) {
            const int r = wr + it * 8;
            float4 v = *reinterpret_cast<const float4*>(
                W + (size_t)(kk + r) * NH + wc);
            *reinterpret_cast<uint4*>(&Ws[r * WS_S + wc]) = f4tf(v);
        }
        __syncthreads();

#pragma unroll
        for (int dc = 0; dc < 4; ++dc) {
            unsigned a[2][4];
#pragma unroll
            for (int mt = 0; mt < 2; ++mt) {
                const int rb = mrow + mt * 16;
                a[mt][0] = __float_as_uint(Xs[(rb + g)     * XS_S + dc * 8 + t]);
                a[mt][1] = __float_as_uint(Xs[(rb + g + 8) * XS_S + dc * 8 + t]);
                a[mt][2] = __float_as_uint(Xs[(rb + g)     * XS_S + dc * 8 + t + 4]);
                a[mt][3] = __float_as_uint(Xs[(rb + g + 8) * XS_S + dc * 8 + t + 4]);
            }
#pragma unroll
            for (int nt = 0; nt < 8; ++nt) {
                unsigned b0 = __float_as_uint(Ws[(dc * 8 + t)     * WS_S + nt * 8 + g]);
                unsigned b1 = __float_as_uint(Ws[(dc * 8 + t + 4) * WS_S + nt * 8 + g]);
                mma8(acc[0][nt], a[0][0], a[0][1], a[0][2], a[0][3], b0, b1);
                mma8(acc[1][nt], a[1][0], a[1][1], a[1][2], a[1][3], b0, b1);
            }
        }
        __syncthreads();
    }

    // epilogue: tf32-round; Q pre-scaled by 1/8 (exact); V transposed
    const float sc = (z == 0) ? 0.125f : 1.0f;
#pragma unroll
    for (int mt = 0; mt < 2; ++mt) {
        const int rb = row0 + mrow + mt * 16;
#pragma unroll
        for (int nt = 0; nt < 8; ++nt) {
            const int col = nt * 8 + 2 * t;
            const int rA = rb + g, rB2 = rb + g + 8;
            const unsigned v0 = f2tf(acc[mt][nt][0] * sc);
            const unsigned v1 = f2tf(acc[mt][nt][1] * sc);
            const unsigned v2 = f2tf(acc[mt][nt][2] * sc);
            const unsigned v3 = f2tf(acc[mt][nt][3] * sc);
            if (z == 2) {
                const int bA = rA >> 11, nA = rA & 2047;
                const int bB = rB2 >> 11, nB = rB2 & 2047;
                g_V[((size_t)bA * NH + col)     * NS + nA] = __uint_as_float(v0);
                g_V[((size_t)bA * NH + col + 1) * NS + nA] = __uint_as_float(v1);
                g_V[((size_t)bB * NH + col)     * NS + nB] = __uint_as_float(v2);
                g_V[((size_t)bB * NH + col + 1) * NS + nB] = __uint_as_float(v3);
            } else {
                float* __restrict__ Out = (z == 0) ? g_Q : g_K;
                *reinterpret_cast<uint2*>(Out + (size_t)rA * NH + col) =
                    make_uint2(v0, v1);
                *reinterpret_cast<uint2*>(Out + (size_t)rB2 * NH + col) =
                    make_uint2(v2, v3);
            }
        }
    }
}

// ---------------------------------------------------------------------------
// Kernel 2: causal flash attention, tf32 mma + ldmatrix + split-K x4 +
// cp.async double-buffered K/V pipeline. Exact R13 except the 0.125 scaling
// is gone (folded into Q — bit-identical); diagonal mask is predicated only.
// ---------------------------------------------------------------------------
__global__ __launch_bounds__(128, 3) void attn_kernel()
{
    extern __shared__ float sm[];

    const int b    = blockIdx.y;
    const int qt   = (NQT - 1) - blockIdx.x;
    const int spl  = blockIdx.z;
    const int q0   = qt * 64;
    const int tid  = threadIdx.x;
    const int wrp  = tid >> 5;
    const int lane = tid & 31;
    const int g    = lane >> 2;
    const int t    = lane & 3;
    const int w16  = wrp * 16;

    const int T  = qt + 1;
    const int tb = (T * spl) >> 2;
    const int te = (T * (spl + 1)) >> 2;

    const float* __restrict__ Qb = g_Q + (size_t)b * NS * NH;
    const float* __restrict__ Kb = g_K + (size_t)b * NS * NH;
    const float* __restrict__ Vb = g_V + (size_t)b * NH * NS;

    const unsigned smb = (unsigned)__cvta_generic_to_shared(sm);
    const int rowA = w16 + (lane & 15);
    const int colA = (lane >> 4) * 4;
    const unsigned fragA = (unsigned)((rowA * SKA + colA) * 4);
    const int rowB = (lane & 7) | ((lane >> 1) & 8);
    const int colB = ((lane >> 3) & 1) * 4;
    const unsigned fragB = (unsigned)((rowB * SKA + colB) * 4);
    const unsigned bufK[2] = { 0u, 2u * STG * 4 };
    const unsigned bufV[2] = { 1u * STG * 4, 3u * STG * 4 };

    const int lr  = tid >> 1;
    const int lc  = (tid & 1) * 32;
    const unsigned kdst0 = (unsigned)((lr * SKA + lc) * 4);
    const float* ksrc_base = Kb + (size_t)lr * NH + lc;
    const float* vsrc_base = Vb + (size_t)lr * NS + lc;

    unsigned qf[8][4];
    if (tb < te) {
        const float4* qp = reinterpret_cast<const float4*>(
            Qb + (size_t)(q0 + lr) * NH + lc);
#pragma unroll
        for (int u = 0; u < 8; ++u)
            *reinterpret_cast<float4*>(&sm[lr * SKA + lc + u * 4]) = qp[u];
        __syncthreads();
#pragma unroll
        for (int dc = 0; dc < 8; ++dc)
            ldsm4(qf[dc][0], qf[dc][1], qf[dc][2], qf[dc][3],
                  smb + fragA + dc * 32);
        __syncthreads();

        {
            const int k0 = tb * 64;
            const float* ks = ksrc_base + (size_t)k0 * NH;
            const float* vs = vsrc_base + k0;
#pragma unroll
            for (int u = 0; u < 8; ++u) {
                cpa16(smb + bufK[0] + kdst0 + u * 16, ks + u * 4);
                cpa16(smb + bufV[0] + kdst0 + u * 16, vs + u * 4);
            }
            CP_COMMIT();
        }
    }

    float o[8][4];
#pragma unroll
    for (int nt = 0; nt < 8; ++nt)
#pragma unroll
        for (int r = 0; r < 4; ++r) o[nt][r] = 0.0f;
    float mA = -1e30f, mB = -1e30f;
    float lA = 0.0f,   lB = 0.0f;

    int cur = 0;
    for (int kt = tb; kt < te; ++kt) {
        CP_WAIT0();
        __syncthreads();

        if (kt + 1 < te) {
            const int k0n = (kt + 1) * 64;
            const float* ks = ksrc_base + (size_t)k0n * NH;
            const float* vs = vsrc_base + k0n;
#pragma unroll
            for (int u = 0; u < 8; ++u) {
                cpa16(smb + bufK[cur ^ 1] + kdst0 + u * 16, ks + u * 4);
                cpa16(smb + bufV[cur ^ 1] + kdst0 + u * 16, vs + u * 4);
            }
            CP_COMMIT();
        }

        float s[8][4];
#pragma unroll
        for (int nt = 0; nt < 8; ++nt)
#pragma unroll
            for (int r = 0; r < 4; ++r) s[nt][r] = 0.0f;

        const unsigned bKc = smb + bufK[cur] + fragB;
#pragma unroll
        for (int dc = 0; dc < 8; ++dc) {
#pragma unroll
            for (int p = 0; p < 4; ++p) {
                unsigned b0, b1, b2, b3;
                ldsm4(b0, b1, b2, b3, bKc + p * (16 * SKA * 4) + dc * 32);
                mma8(s[2 * p],     qf[dc][0], qf[dc][1], qf[dc][2], qf[dc][3], b0, b1);
                mma8(s[2 * p + 1], qf[dc][0], qf[dc][1], qf[dc][2], qf[dc][3], b2, b3);
            }
        }

        if (kt == qt) {   // causal mask on the diagonal tile (S pre-scaled via Q)
            const int rA = w16 + g, rB2 = w16 + g + 8;
#pragma unroll
            for (int nt = 0; nt < 8; ++nt) {
                const int c0 = nt * 8 + 2 * t, c1 = c0 + 1;
                if (c0 > rA)  s[nt][0] = -1e30f;
                if (c1 > rA)  s[nt][1] = -1e30f;
                if (c0 > rB2) s[nt][2] = -1e30f;
                if (c1 > rB2) s[nt][3] = -1e30f;
            }
        }

        float cmA = -1e30f, cmB = -1e30f;
#pragma unroll
        for (int nt = 0; nt < 8; ++nt) {
            cmA = fmaxf(cmA, fmaxf(s[nt][0], s[nt][1]));
            cmB = fmaxf(cmB, fmaxf(s[nt][2], s[nt][3]));
        }
        cmA = fmaxf(cmA, __shfl_xor_sync(0xffffffffu, cmA, 1));
        cmA = fmaxf(cmA, __shfl_xor_sync(0xffffffffu, cmA, 2));
        cmB = fmaxf(cmB, __shfl_xor_sync(0xffffffffu, cmB, 1));
        cmB = fmaxf(cmB, __shfl_xor_sync(0xffffffffu, cmB, 2));

        const float mnA = fmaxf(mA, cmA);
        const float mnB = fmaxf(mB, cmB);
        const float cA  = __expf(mA - mnA);
        const float cB  = __expf(mB - mnB);
        mA = mnA; mB = mnB;
        lA *= cA; lB *= cB;
#pragma unroll
        for (int nt = 0; nt < 8; ++nt) {
            o[nt][0] *= cA; o[nt][1] *= cA;
            o[nt][2] *= cB; o[nt][3] *= cB;
        }
#pragma unroll
        for (int nt = 0; nt < 8; ++nt) {
            s[nt][0] = __expf(s[nt][0] - mnA);
            s[nt][1] = __expf(s[nt][1] - mnA);
            s[nt][2] = __expf(s[nt][2] - mnB);
            s[nt][3] = __expf(s[nt][3] - mnB);
            lA += s[nt][0] + s[nt][1];
            lB += s[nt][2] + s[nt][3];
        }

        __syncthreads();

        float* Kcur = sm + (cur ? 2 * STG : 0);
#pragma unroll
        for (int nt = 0; nt < 8; ++nt) {
            *reinterpret_cast<uint2*>(&Kcur[(w16 + g) * SKA + nt * 8 + 2 * t]) =
                make_uint2(f2tf(s[nt][0]), f2tf(s[nt][1]));
            *reinterpret_cast<uint2*>(&Kcur[(w16 + g + 8) * SKA + nt * 8 + 2 * t]) =
                make_uint2(f2tf(s[nt][2]), f2tf(s[nt][3]));
        }
        __syncwarp();

        const unsigned aPc = smb + bufK[cur] + fragA;
        const unsigned bVc = smb + bufV[cur] + fragB;
#pragma unroll
        for (int kc = 0; kc < 8; ++kc) {
            unsigned a0, a1, a2, a3;
            ldsm4(a0, a1, a2, a3, aPc + kc * 32);
#pragma unroll
            for (int p = 0; p < 4; ++p) {
                unsigned b0, b1, b2, b3;
                ldsm4(b0, b1, b2, b3, bVc + p * (16 * SKA * 4) + kc * 32);
                mma8(o[2 * p],     a0, a1, a2, a3, b0, b1);
                mma8(o[2 * p + 1], a0, a1, a2, a3, b2, b3);
            }
        }

        cur ^= 1;
    }

    lA += __shfl_xor_sync(0xffffffffu, lA, 1);
    lA += __shfl_xor_sync(0xffffffffu, lA, 2);
    lB += __shfl_xor_sync(0xffffffffu, lB, 1);
    lB += __shfl_xor_sync(0xffffffffu, lB, 2);

    const size_t slot = ((size_t)spl * NB + b) * NQT + qt;
    float* op = g_Op + slot * 64 * 64;
#pragma unroll
    for (int nt = 0; nt < 8; ++nt) {
        *reinterpret_cast<float2*>(op + (w16 + g) * 64 + nt * 8 + 2 * t) =
            make_float2(o[nt][0], o[nt][1]);
        *reinterpret_cast<float2*>(op + (w16 + g + 8) * 64 + nt * 8 + 2 * t) =
            make_float2(o[nt][2], o[nt][3]);
    }
    if (t == 0) {
        g_M[slot * 64 + w16 + g]     = mA;
        g_M[slot * 64 + w16 + g + 8] = mB;
        g_L[slot * 64 + w16 + g]     = lA;
        g_L[slot * 64 + w16 + g + 8] = lB;
    }
}

// ---------------------------------------------------------------------------
// Kernel 3: merge NSPL split-K partials. grid (32, NB), 256 threads (R13).
// ---------------------------------------------------------------------------
__global__ __launch_bounds__(256) void merge_kernel(float* __restrict__ out)
{
    const int qt  = blockIdx.x;
    const int b   = blockIdx.y;
    const int tid = threadIdx.x;
    const int r   = tid >> 2;
    const int cs  = (tid & 3) * 16;

    size_t slot[NSPL];
    float  m[NSPL], l[NSPL];
    float  M = -1e30f;
#pragma unroll
    for (int s = 0; s < NSPL; ++s) {
        slot[s] = ((size_t)s * NB + b) * NQT + qt;
        m[s] = g_M[slot[s] * 64 + r];
        l[s] = g_L[slot[s] * 64 + r];
        M = fmaxf(M, m[s]);
    }
    float f[NSPL], den = 0.0f;
#pragma unroll
    for (int s = 0; s < NSPL; ++s) {
        f[s] = __expf(m[s] - M);     // empty split: exp(-1e30 - M) = 0
        den += l[s] * f[s];
    }
    const float inv = 1.0f / den;
#pragma unroll
    for (int s = 0; s < NSPL; ++s) f[s] *= inv;

    float4* po = reinterpret_cast<float4*>(
        out + ((size_t)b * NS + qt * 64 + r) * NH + cs);

#pragma unroll
    for (int u = 0; u < 4; ++u) {
        float4 acc = make_float4(0.f, 0.f, 0.f, 0.f);
#pragma unroll
        for (int s = 0; s < NSPL; ++s) {
            float4 v = *reinterpret_cast<const float4*>(
                g_Op + slot[s] * 4096 + r * 64 + cs + u * 4);
            acc.x += v.x * f[s]; acc.y += v.y * f[s];
            acc.z += v.z * f[s]; acc.w += v.w * f[s];
        }
        po[u] = acc;
    }
}

// ---------------------------------------------------------------------------
extern "C" void kernel_launch(void* const* d_in, const int* in_sizes, int n_in,
                              void* d_out, int out_size)
{
    const float* X  = (const float*)d_in[0];
    const float* Wq = (const float*)d_in[1];
    const float* Wk = (const float*)d_in[2];
    const float* Wv = (const float*)d_in[3];
    float* out = (float*)d_out;

    const int attn_smem = 4 * STG * (int)sizeof(float);   // 69632 B
    cudaFuncSetAttribute(attn_kernel,
                         cudaFuncAttributeMaxDynamicSharedMemorySize, attn_smem);

    proj_kernel<<<dim3((NB * NS) / 128, 1, 3), 128>>>(X, Wq, Wk, Wv);
    attn_kernel<<<dim3(NQT, NB, NSPL), 128, attn_smem>>>();
    merge_kernel<<<dim3(NQT, NB), 256>>>(out);
}

// round 17
// speedup vs baseline: 1.1005x; 1.0020x over previous
#include <cuda_runtime.h>

#define NB 8
#define NS 2048
#define ND 768
#define NH 64
#define NQT 32            // q-tiles of 64
#define NSPL 4            // split-K factor
#define SKA 68            // attn smem stride (floats), 68 % 32 == 4 -> conflict-free LDSM
#define STG (64 * SKA)    // floats per attn K/V buffer

// g_Q (pre-scaled by 0.125*log2e), g_K: [b][n][h] tf32 bits.
// g_V: [b][h][n] tf32 bits (pre-transposed). Scores are in log2 domain.
__device__ float g_Q[NB * NS * NH];
__device__ float g_K[NB * NS * NH];
__device__ float g_V[NB * NH * NS];

// split-K partials: [split][b][qt] -> 64x64 unnormalized O, plus per-row m,l
// (m is in log2 domain)
__device__ float g_Op[NSPL * NB * NQT * 64 * 64];
__device__ float g_M[NSPL * NB * NQT * 64];
__device__ float g_L[NSPL * NB * NQT * 64];

// ---------------------------------------------------------------------------
// helpers
// ---------------------------------------------------------------------------
__device__ __forceinline__ unsigned f2tf(float f) {
    unsigned u;
    asm("cvt.rna.tf32.f32 %0, %1;" : "=r"(u) : "f"(f));
    return u;
}
__device__ __forceinline__ uint4 f4tf(float4 v) {
    uint4 r;
    r.x = f2tf(v.x); r.y = f2tf(v.y); r.z = f2tf(v.z); r.w = f2tf(v.w);
    return r;
}
__device__ __forceinline__ void mma8(float c[4],
                                     unsigned a0, unsigned a1, unsigned a2, unsigned a3,
                                     unsigned b0, unsigned b1) {
    asm("mma.sync.aligned.m16n8k8.row.col.f32.tf32.tf32.f32 "
        "{%0,%1,%2,%3}, {%4,%5,%6,%7}, {%8,%9}, {%0,%1,%2,%3};"
        : "+f"(c[0]), "+f"(c[1]), "+f"(c[2]), "+f"(c[3])
        : "r"(a0), "r"(a1), "r"(a2), "r"(a3), "r"(b0), "r"(b1));
}
__device__ __forceinline__ void ldsm4(unsigned &r0, unsigned &r1,
                                      unsigned &r2, unsigned &r3, unsigned addr) {
    asm volatile("ldmatrix.sync.aligned.m8n8.x4.shared.b16 {%0,%1,%2,%3}, [%4];"
                 : "=r"(r0), "=r"(r1), "=r"(r2), "=r"(r3) : "r"(addr));
}
__device__ __forceinline__ void cpa16(unsigned dst, const void* src) {
    asm volatile("cp.async.cg.shared.global [%0], [%1], 16;"
                 :: "r"(dst), "l"(src));
}
#define CP_COMMIT() asm volatile("cp.async.commit_group;" ::: "memory")
#define CP_WAIT0()  asm volatile("cp.async.wait_group 0;" ::: "memory")

// 0.125 * log2(e): folds both the softmax scale and the exp->exp2 conversion
#define QSCALE 0.18033688011112042f

// ---------------------------------------------------------------------------
// Kernel 1: QKV projection via tf32 mma — frozen R13/R8 structure.
// Epilogue: Q pre-scaled by QSCALE; V stored transposed; tf32 bits out.
// ---------------------------------------------------------------------------
#define XS_S 36
#define WS_S 72

__global__ __launch_bounds__(128, 3) void proj_kernel(
    const float* __restrict__ X,
    const float* __restrict__ Wq,
    const float* __restrict__ Wk,
    const float* __restrict__ Wv)
{
    const int z = blockIdx.z;
    const float* __restrict__ W = (z == 0) ? Wq : (z == 1) ? Wk : Wv;

    __shared__ float Xs[128 * XS_S];
    __shared__ float Ws[32 * WS_S];

    const int row0 = blockIdx.x * 128;
    const int tid  = threadIdx.x;
    const int wrp  = tid >> 5;
    const int lane = tid & 31;
    const int g    = lane >> 2;
    const int t    = lane & 3;
    const int mrow = wrp * 32;

    float acc[2][8][4];
#pragma unroll
    for (int mt = 0; mt < 2; ++mt)
#pragma unroll
        for (int nt = 0; nt < 8; ++nt)
#pragma unroll
            for (int r = 0; r < 4; ++r) acc[mt][nt][r] = 0.0f;

    const int xr = tid >> 3;
    const int xc = (tid & 7) * 4;
    const int wr = tid >> 4;
    const int wc = (tid & 15) * 4;

    for (int kk = 0; kk < ND; kk += 32) {
#pragma unroll
        for (int it = 0; it < 8; ++it) {
            const int r = xr + it * 16;
            float4 v = *reinterpret_cast<const float4*>(
                X + (size_t)(row0 + r) * ND + kk + xc);
            *reinterpret_cast<uint4*>(&Xs[r * XS_S + xc]) = f4tf(v);
        }
#pragma unroll
        for (int it = 0; it < 4; ++it) {
            const int r = wr + it * 8;
            float4 v = *reinterpret_cast<const float4*>(
                W + (size_t)(kk + r) * NH + wc);
            *reinterpret_cast<uint4*>(&Ws[r * WS_S + wc]) = f4tf(v);
        }
        __syncthreads();

#pragma unroll
        for (int dc = 0; dc < 4; ++dc) {
            unsigned a[2][4];
#pragma unroll
            for (int mt = 0; mt < 2; ++mt) {
                const int rb = mrow + mt * 16;
                a[mt][0] = __float_as_uint(Xs[(rb + g)     * XS_S + dc * 8 + t]);
                a[mt][1] = __float_as_uint(Xs[(rb + g + 8) * XS_S + dc * 8 + t]);
                a[mt][2] = __float_as_uint(Xs[(rb + g)     * XS_S + dc * 8 + t + 4]);
                a[mt][3] = __float_as_uint(Xs[(rb + g + 8) * XS_S + dc * 8 + t + 4]);
            }
#pragma unroll
            for (int nt = 0; nt < 8; ++nt) {
                unsigned b0 = __float_as_uint(Ws[(dc * 8 + t)     * WS_S + nt * 8 + g]);
                unsigned b1 = __float_as_uint(Ws[(dc * 8 + t + 4) * WS_S + nt * 8 + g]);
                mma8(acc[0][nt], a[0][0], a[0][1], a[0][2], a[0][3], b0, b1);
                mma8(acc[1][nt], a[1][0], a[1][1], a[1][2], a[1][3], b0, b1);
            }
        }
        __syncthreads();
    }

    // epilogue: tf32-round; Q pre-scaled by 0.125*log2e; V transposed
    const float sc = (z == 0) ? QSCALE : 1.0f;
#pragma unroll
    for (int mt = 0; mt < 2; ++mt) {
        const int rb = row0 + mrow + mt * 16;
#pragma unroll
        for (int nt = 0; nt < 8; ++nt) {
            const int col = nt * 8 + 2 * t;
            const int rA = rb + g, rB2 = rb + g + 8;
            const unsigned v0 = f2tf(acc[mt][nt][0] * sc);
            const unsigned v1 = f2tf(acc[mt][nt][1] * sc);
            const unsigned v2 = f2tf(acc[mt][nt][2] * sc);
            const unsigned v3 = f2tf(acc[mt][nt][3] * sc);
            if (z == 2) {
                const int bA = rA >> 11, nA = rA & 2047;
                const int bB = rB2 >> 11, nB = rB2 & 2047;
                g_V[((size_t)bA * NH + col)     * NS + nA] = __uint_as_float(v0);
                g_V[((size_t)bA * NH + col + 1) * NS + nA] = __uint_as_float(v1);
                g_V[((size_t)bB * NH + col)     * NS + nB] = __uint_as_float(v2);
                g_V[((size_t)bB * NH + col + 1) * NS + nB] = __uint_as_float(v3);
            } else {
                float* __restrict__ Out = (z == 0) ? g_Q : g_K;
                *reinterpret_cast<uint2*>(Out + (size_t)rA * NH + col) =
                    make_uint2(v0, v1);
                *reinterpret_cast<uint2*>(Out + (size_t)rB2 * NH + col) =
                    make_uint2(v2, v3);
            }
        }
    }
}

// ---------------------------------------------------------------------------
// Kernel 2: causal flash attention, tf32 mma + ldmatrix + split-K x4 +
// cp.async double-buffered K/V pipeline. Softmax in log2 domain (exp2f).
// ---------------------------------------------------------------------------
__global__ __launch_bounds__(128, 3) void attn_kernel()
{
    extern __shared__ float sm[];

    const int b    = blockIdx.y;
    const int qt   = (NQT - 1) - blockIdx.x;
    const int spl  = blockIdx.z;
    const int q0   = qt * 64;
    const int tid  = threadIdx.x;
    const int wrp  = tid >> 5;
    const int lane = tid & 31;
    const int g    = lane >> 2;
    const int t    = lane & 3;
    const int w16  = wrp * 16;

    const int T  = qt + 1;
    const int tb = (T * spl) >> 2;
    const int te = (T * (spl + 1)) >> 2;

    const float* __restrict__ Qb = g_Q + (size_t)b * NS * NH;
    const float* __restrict__ Kb = g_K + (size_t)b * NS * NH;
    const float* __restrict__ Vb = g_V + (size_t)b * NH * NS;

    const unsigned smb = (unsigned)__cvta_generic_to_shared(sm);
    const int rowA = w16 + (lane & 15);
    const int colA = (lane >> 4) * 4;
    const unsigned fragA = (unsigned)((rowA * SKA + colA) * 4);
    const int rowB = (lane & 7) | ((lane >> 1) & 8);
    const int colB = ((lane >> 3) & 1) * 4;
    const unsigned fragB = (unsigned)((rowB * SKA + colB) * 4);
    const unsigned bufK[2] = { 0u, 2u * STG * 4 };
    const unsigned bufV[2] = { 1u * STG * 4, 3u * STG * 4 };

    const int lr  = tid >> 1;
    const int lc  = (tid & 1) * 32;
    const unsigned kdst0 = (unsigned)((lr * SKA + lc) * 4);
    const float* ksrc_base = Kb + (size_t)lr * NH + lc;
    const float* vsrc_base = Vb + (size_t)lr * NS + lc;

    unsigned qf[8][4];
    if (tb < te) {
        const float4* qp = reinterpret_cast<const float4*>(
            Qb + (size_t)(q0 + lr) * NH + lc);
#pragma unroll
        for (int u = 0; u < 8; ++u)
            *reinterpret_cast<float4*>(&sm[lr * SKA + lc + u * 4]) = qp[u];
        __syncthreads();
#pragma unroll
        for (int dc = 0; dc < 8; ++dc)
            ldsm4(qf[dc][0], qf[dc][1], qf[dc][2], qf[dc][3],
                  smb + fragA + dc * 32);
        __syncthreads();

        {
            const int k0 = tb * 64;
            const float* ks = ksrc_base + (size_t)k0 * NH;
            const float* vs = vsrc_base + k0;
#pragma unroll
            for (int u = 0; u < 8; ++u) {
                cpa16(smb + bufK[0] + kdst0 + u * 16, ks + u * 4);
                cpa16(smb + bufV[0] + kdst0 + u * 16, vs + u * 4);
            }
            CP_COMMIT();
        }
    }

    float o[8][4];
#pragma unroll
    for (int nt = 0; nt < 8; ++nt)
#pragma unroll
        for (int r = 0; r < 4; ++r) o[nt][r] = 0.0f;
    float mA = -1e30f, mB = -1e30f;
    float lA = 0.0f,   lB = 0.0f;

    int cur = 0;
    for (int kt = tb; kt < te; ++kt) {
        CP_WAIT0();
        __syncthreads();

        if (kt + 1 < te) {
            const int k0n = (kt + 1) * 64;
            const float* ks = ksrc_base + (size_t)k0n * NH;
            const float* vs = vsrc_base + k0n;
#pragma unroll
            for (int u = 0; u < 8; ++u) {
                cpa16(smb + bufK[cur ^ 1] + kdst0 + u * 16, ks + u * 4);
                cpa16(smb + bufV[cur ^ 1] + kdst0 + u * 16, vs + u * 4);
            }
            CP_COMMIT();
        }

        float s[8][4];
#pragma unroll
        for (int nt = 0; nt < 8; ++nt)
#pragma unroll
            for (int r = 0; r < 4; ++r) s[nt][r] = 0.0f;

        const unsigned bKc = smb + bufK[cur] + fragB;
#pragma unroll
        for (int dc = 0; dc < 8; ++dc) {
#pragma unroll
            for (int p = 0; p < 4; ++p) {
                unsigned b0, b1, b2, b3;
                ldsm4(b0, b1, b2, b3, bKc + p * (16 * SKA * 4) + dc * 32);
                mma8(s[2 * p],     qf[dc][0], qf[dc][1], qf[dc][2], qf[dc][3], b0, b1);
                mma8(s[2 * p + 1], qf[dc][0], qf[dc][1], qf[dc][2], qf[dc][3], b2, b3);
            }
        }

        if (kt == qt) {   // causal mask on the diagonal tile
            const int rA = w16 + g, rB2 = w16 + g + 8;
#pragma unroll
            for (int nt = 0; nt < 8; ++nt) {
                const int c0 = nt * 8 + 2 * t, c1 = c0 + 1;
                if (c0 > rA)  s[nt][0] = -1e30f;
                if (c1 > rA)  s[nt][1] = -1e30f;
                if (c0 > rB2) s[nt][2] = -1e30f;
                if (c1 > rB2) s[nt][3] = -1e30f;
            }
        }

        float cmA = -1e30f, cmB = -1e30f;
#pragma unroll
        for (int nt = 0; nt < 8; ++nt) {
            cmA = fmaxf(cmA, fmaxf(s[nt][0], s[nt][1]));
            cmB = fmaxf(cmB, fmaxf(s[nt][2], s[nt][3]));
        }
        cmA = fmaxf(cmA, __shfl_xor_sync(0xffffffffu, cmA, 1));
        cmA = fmaxf(cmA, __shfl_xor_sync(0xffffffffu, cmA, 2));
        cmB = fmaxf(cmB, __shfl_xor_sync(0xffffffffu, cmB, 1));
        cmB = fmaxf(cmB, __shfl_xor_sync(0xffffffffu, cmB, 2));

        const float mnA = fmaxf(mA, cmA);
        const float mnB = fmaxf(mB, cmB);
        const float cA  = exp2f(mA - mnA);   // log2-domain correction
        const float cB  = exp2f(mB - mnB);
        mA = mnA; mB = mnB;
        lA *= cA; lB *= cB;
#pragma unroll
        for (int nt = 0; nt < 8; ++nt) {
            o[nt][0] *= cA; o[nt][1] *= cA;
            o[nt][2] *= cB; o[nt][3] *= cB;
        }
#pragma unroll
        for (int nt = 0; nt < 8; ++nt) {
            s[nt][0] = exp2f(s[nt][0] - mnA);
            s[nt][1] = exp2f(s[nt][1] - mnA);
            s[nt][2] = exp2f(s[nt][2] - mnB);
            s[nt][3] = exp2f(s[nt][3] - mnB);
            lA += s[nt][0] + s[nt][1];
            lB += s[nt][2] + s[nt][3];
        }

        __syncthreads();

        float* Kcur = sm + (cur ? 2 * STG : 0);
#pragma unroll
        for (int nt = 0; nt < 8; ++nt) {
            *reinterpret_cast<uint2*>(&Kcur[(w16 + g) * SKA + nt * 8 + 2 * t]) =
                make_uint2(f2tf(s[nt][0]), f2tf(s[nt][1]));
            *reinterpret_cast<uint2*>(&Kcur[(w16 + g + 8) * SKA + nt * 8 + 2 * t]) =
                make_uint2(f2tf(s[nt][2]), f2tf(s[nt][3]));
        }
        __syncwarp();

        const unsigned aPc = smb + bufK[cur] + fragA;
        const unsigned bVc = smb + bufV[cur] + fragB;
#pragma unroll
        for (int kc = 0; kc < 8; ++kc) {
            unsigned a0, a1, a2, a3;
            ldsm4(a0, a1, a2, a3, aPc + kc * 32);
#pragma unroll
            for (int p = 0; p < 4; ++p) {
                unsigned b0, b1, b2, b3;
                ldsm4(b0, b1, b2, b3, bVc + p * (16 * SKA * 4) + kc * 32);
                mma8(o[2 * p],     a0, a1, a2, a3, b0, b1);
                mma8(o[2 * p + 1], a0, a1, a2, a3, b2, b3);
            }
        }

        cur ^= 1;
    }

    lA += __shfl_xor_sync(0xffffffffu, lA, 1);
    lA += __shfl_xor_sync(0xffffffffu, lA, 2);
    lB += __shfl_xor_sync(0xffffffffu, lB, 1);
    lB += __shfl_xor_sync(0xffffffffu, lB, 2);

    const size_t slot = ((size_t)spl * NB + b) * NQT + qt;
    float* op = g_Op + slot * 64 * 64;
#pragma unroll
    for (int nt = 0; nt < 8; ++nt) {
        *reinterpret_cast<float2*>(op + (w16 + g) * 64 + nt * 8 + 2 * t) =
            make_float2(o[nt][0], o[nt][1]);
        *reinterpret_cast<float2*>(op + (w16 + g + 8) * 64 + nt * 8 + 2 * t) =
            make_float2(o[nt][2], o[nt][3]);
    }
    if (t == 0) {
        g_M[slot * 64 + w16 + g]     = mA;
        g_M[slot * 64 + w16 + g + 8] = mB;
        g_L[slot * 64 + w16 + g]     = lA;
        g_L[slot * 64 + w16 + g + 8] = lB;
    }
}

// ---------------------------------------------------------------------------
// Kernel 3: merge NSPL split-K partials (log2-domain m). grid (32, NB, 2),
// 128 threads: each z-half handles 32 q-rows.
// ---------------------------------------------------------------------------
__global__ __launch_bounds__(128) void merge_kernel(float* __restrict__ out)
{
    const int qt  = blockIdx.x;
    const int b   = blockIdx.y;
    const int tid = threadIdx.x;
    const int r   = blockIdx.z * 32 + (tid >> 2);
    const int cs  = (tid & 3) * 16;

    size_t slot[NSPL];
    float  m[NSPL], l[NSPL];
    float  M = -1e30f;
#pragma unroll
    for (int s = 0; s < NSPL; ++s) {
        slot[s] = ((size_t)s * NB + b) * NQT + qt;
        m[s] = g_M[slot[s] * 64 + r];
        l[s] = g_L[slot[s] * 64 + r];
        M = fmaxf(M, m[s]);
    }
    float f[NSPL], den = 0.0f;
#pragma unroll
    for (int s = 0; s < NSPL; ++s) {
        f[s] = exp2f(m[s] - M);     // empty split: exp2(-1e30 - M) = 0
        den += l[s] * f[s];
    }
    const float inv = 1.0f / den;
#pragma unroll
    for (int s = 0; s < NSPL; ++s) f[s] *= inv;

    float4* po = reinterpret_cast<float4*>(
        out + ((size_t)b * NS + qt * 64 + r) * NH + cs);

#pragma unroll
    for (int u = 0; u < 4; ++u) {
        float4 acc = make_float4(0.f, 0.f, 0.f, 0.f);
#pragma unroll
        for (int s = 0; s < NSPL; ++s) {
            float4 v = *reinterpret_cast<const float4*>(
                g_Op + slot[s] * 4096 + r * 64 + cs + u * 4);
            acc.x += v.x * f[s]; acc.y += v.y * f[s];
            acc.z += v.z * f[s]; acc.w += v.w * f[s];
        }
        po[u] = acc;
    }
}

// ---------------------------------------------------------------------------
extern "C" void kernel_launch(void* const* d_in, const int* in_sizes, int n_in,
                              void* d_out, int out_size)
{
    const float* X  = (const float*)d_in[0];
    const float* Wq = (const float*)d_in[1];
    const float* Wk = (const float*)d_in[2];
    const float* Wv = (const float*)d_in[3];
    float* out = (float*)d_out;

    const int attn_smem = 4 * STG * (int)sizeof(float);   // 69632 B
    cudaFuncSetAttribute(attn_kernel,
                         cudaFuncAttributeMaxDynamicSharedMemorySize, attn_smem);

    proj_kernel<<<dim3((NB * NS) / 128, 1, 3), 128>>>(X, Wq, Wk, Wv);
    attn_kernel<<<dim3(NQT, NB, NSPL), 128, attn_smem>>>();
    merge_kernel<<<dim3(NQT, NB, 2), 128>>>(out);
}